// round 1
// baseline (speedup 1.0000x reference)
#include <cuda_runtime.h>
#include <math.h>

// Problem constants
#define B_  2
#define T_  2048
#define E_  1024
#define H_  16
#define D_  64
#define BH_ (B_*H_)       // 32

// ---------------------------------------------------------------------------
// Device scratch (static globals: no runtime allocation)
// ---------------------------------------------------------------------------
__device__ float g_q[(size_t)BH_ * T_ * D_];                 // 16 MB
__device__ float g_k[(size_t)BH_ * T_ * D_];                 // 16 MB
__device__ float g_v[(size_t)BH_ * T_ * D_];                 // 16 MB
__device__ float g_s[(size_t)BH_ * T_ * T_];                 // 512 MB scores -> exp(scores - colmax)
__device__ float g_zinv[(size_t)BH_ * T_];                   // 256 KB per-column 1/sum

// ---------------------------------------------------------------------------
// Kernel 1: per-head linear projection  out[b,h,t,d] = X[b,t,:] @ W[h,:,d] + bias[h,d]
// Treated as GEMM rows = B*T (4096), cols per block = one head's D=64, K=E=1024.
// grid (BT/64, H), 256 threads, 4x4 microtile, BK=32.
// ---------------------------------------------------------------------------
__global__ void proj_kernel(const float* __restrict__ X,
                            const float* __restrict__ W,
                            const float* __restrict__ bias,
                            float* __restrict__ out)
{
    __shared__ float As[32][65];   // [k][m] (transposed), pad 65 to break conflicts
    __shared__ float Bs[32][65];   // [k][n]

    const int m0  = blockIdx.x * 64;   // row block within B*T
    const int h   = blockIdx.y;
    const int tid = threadIdx.x;
    const int tx  = tid & 15;
    const int ty  = tid >> 4;

    float acc[4][4] = {};

    for (int k0 = 0; k0 < E_; k0 += 32) {
        // X tile: 64 rows x 32 k, store transposed
        #pragma unroll
        for (int i = tid; i < 512; i += 256) {
            int row = i >> 3;
            int c4  = (i & 7) * 4;
            float4 v = *reinterpret_cast<const float4*>(
                X + (size_t)(m0 + row) * E_ + k0 + c4);
            As[c4 + 0][row] = v.x;
            As[c4 + 1][row] = v.y;
            As[c4 + 2][row] = v.z;
            As[c4 + 3][row] = v.w;
        }
        // W tile: 32 k x 64 d  (W[h][e][d] row stride D)
        #pragma unroll
        for (int i = tid; i < 512; i += 256) {
            int row = i >> 4;
            int c4  = (i & 15) * 4;
            float4 v = *reinterpret_cast<const float4*>(
                W + ((size_t)h * E_ + k0 + row) * D_ + c4);
            Bs[row][c4 + 0] = v.x;
            Bs[row][c4 + 1] = v.y;
            Bs[row][c4 + 2] = v.z;
            Bs[row][c4 + 3] = v.w;
        }
        __syncthreads();

        #pragma unroll 8
        for (int kk = 0; kk < 32; kk++) {
            float a[4], b[4];
            #pragma unroll
            for (int i = 0; i < 4; i++) a[i] = As[kk][ty * 4 + i];
            #pragma unroll
            for (int j = 0; j < 4; j++) b[j] = Bs[kk][tx * 4 + j];
            #pragma unroll
            for (int i = 0; i < 4; i++)
                #pragma unroll
                for (int j = 0; j < 4; j++)
                    acc[i][j] = fmaf(a[i], b[j], acc[i][j]);
        }
        __syncthreads();
    }

    // write to (B,H,T,D)
    #pragma unroll
    for (int i = 0; i < 4; i++) {
        int r  = m0 + ty * 4 + i;
        int bb = r / T_;
        int t  = r - bb * T_;
        float* op = out + (((size_t)bb * H_ + h) * T_ + t) * D_ + tx * 4;
        #pragma unroll
        for (int j = 0; j < 4; j++)
            op[j] = acc[i][j] + bias[h * D_ + tx * 4 + j];
    }
}

// ---------------------------------------------------------------------------
// Kernel 2: scores S[bh,t,s] = scale * Q[bh,t,:] . K[bh,s,:]
// grid (s_tiles=32, t_tiles=32, bh=32); skip strictly-upper tiles (causal).
// K-dim = D = 64 fits entirely in smem: single pass.
// ---------------------------------------------------------------------------
__global__ void scores_kernel(const float* __restrict__ Q,
                              const float* __restrict__ K,
                              float* __restrict__ S)
{
    const int st = blockIdx.x;
    const int tt = blockIdx.y;
    const int bh = blockIdx.z;
    if (st > tt) return;   // entire tile above the diagonal: never needed

    __shared__ float Qs[64][65];   // [d][t] transposed
    __shared__ float Ks[64][65];   // [d][s] transposed

    const int tid = threadIdx.x;
    const int tx  = tid & 15;
    const int ty  = tid >> 4;

    const float* Qp = Q + ((size_t)bh * T_ + tt * 64) * D_;
    const float* Kp = K + ((size_t)bh * T_ + st * 64) * D_;

    #pragma unroll
    for (int i = tid; i < 1024; i += 256) {
        int row = i >> 4;
        int c4  = (i & 15) * 4;
        float4 q4 = *reinterpret_cast<const float4*>(Qp + row * D_ + c4);
        Qs[c4 + 0][row] = q4.x;
        Qs[c4 + 1][row] = q4.y;
        Qs[c4 + 2][row] = q4.z;
        Qs[c4 + 3][row] = q4.w;
        float4 k4 = *reinterpret_cast<const float4*>(Kp + row * D_ + c4);
        Ks[c4 + 0][row] = k4.x;
        Ks[c4 + 1][row] = k4.y;
        Ks[c4 + 2][row] = k4.z;
        Ks[c4 + 3][row] = k4.w;
    }
    __syncthreads();

    float acc[4][4] = {};
    #pragma unroll 8
    for (int dd = 0; dd < 64; dd++) {
        float a[4], b[4];
        #pragma unroll
        for (int i = 0; i < 4; i++) a[i] = Qs[dd][ty * 4 + i];
        #pragma unroll
        for (int j = 0; j < 4; j++) b[j] = Ks[dd][tx * 4 + j];
        #pragma unroll
        for (int i = 0; i < 4; i++)
            #pragma unroll
            for (int j = 0; j < 4; j++)
                acc[i][j] = fmaf(a[i], b[j], acc[i][j]);
    }

    const float scale = 0.125f;   // D^-0.5
    #pragma unroll
    for (int i = 0; i < 4; i++) {
        int t = tt * 64 + ty * 4 + i;
        float* sp = S + ((size_t)bh * T_ + t) * T_ + st * 64 + tx * 4;
        #pragma unroll
        for (int j = 0; j < 4; j++)
            sp[j] = acc[i][j] * scale;
    }
}

// ---------------------------------------------------------------------------
// Kernel 3: column softmax stats (softmax over QUERY axis t, valid t >= s).
// One thread per column (bh, s). Pass 1: max; Pass 2: exp written in place,
// accumulate sum; store 1/sum. Reads coalesced (consecutive s across lanes).
// ---------------------------------------------------------------------------
__global__ void colstats_kernel(float* __restrict__ S,
                                float* __restrict__ zinv)
{
    const int idx = blockIdx.x * blockDim.x + threadIdx.x;   // 0 .. BH*T-1
    const int bh  = idx >> 11;          // /T_
    const int s   = idx & (T_ - 1);
    float* Sp = S + (size_t)bh * T_ * T_ + s;

    const int t0 = s & ~31;             // warp-uniform start (lanes are consecutive s)

    float m = -3.0e38f;
    for (int t = t0; t < T_; t++) {
        if (t >= s) m = fmaxf(m, Sp[(size_t)t * T_]);
    }
    float z = 0.f;
    for (int t = t0; t < T_; t++) {
        if (t >= s) {
            float e = __expf(Sp[(size_t)t * T_] - m);
            z += e;
            Sp[(size_t)t * T_] = e;
        }
    }
    zinv[idx] = 1.0f / z;
}

// ---------------------------------------------------------------------------
// Kernel 4: out[b,t,h*D+d] = sum_{s<=t} P[bh,t,s] * (V[bh,s,d] * zinv[bh,s])
// GEMM M=64-tile of t, N=64 (=D), K over s tiles 0..tt (causal).
// grid (t_tiles=32, bh=32).
// ---------------------------------------------------------------------------
__global__ void pv_kernel(const float* __restrict__ S,
                          const float* __restrict__ V,
                          const float* __restrict__ zinv,
                          float* __restrict__ out)
{
    const int tt = blockIdx.x;
    const int bh = blockIdx.y;
    const int bb = bh >> 4;      // / H
    const int h  = bh & 15;

    __shared__ float Ps[32][65];   // [s][t] transposed
    __shared__ float Vs[32][65];   // [s][d]

    const int tid = threadIdx.x;
    const int tx  = tid & 15;
    const int ty  = tid >> 4;
    const int t0  = tt * 64;

    const float* Sbase = S + (size_t)bh * T_ * T_;

    float acc[4][4] = {};

    for (int s0 = 0; s0 < t0 + 64; s0 += 32) {
        // P tile: rows t0..t0+63, cols s0..s0+31; mask s > t -> 0 (diag tile)
        #pragma unroll
        for (int i = tid; i < 512; i += 256) {
            int row = i >> 3;
            int c4  = (i & 7) * 4;
            int t   = t0 + row;
            float4 p4 = *reinterpret_cast<const float4*>(
                Sbase + (size_t)t * T_ + s0 + c4);
            int sb = s0 + c4;
            Ps[c4 + 0][row] = (sb + 0 <= t) ? p4.x : 0.f;
            Ps[c4 + 1][row] = (sb + 1 <= t) ? p4.y : 0.f;
            Ps[c4 + 2][row] = (sb + 2 <= t) ? p4.z : 0.f;
            Ps[c4 + 3][row] = (sb + 3 <= t) ? p4.w : 0.f;
        }
        // V tile scaled by zinv (fold 1/colsum into V rows)
        #pragma unroll
        for (int i = tid; i < 512; i += 256) {
            int row = i >> 4;
            int c4  = (i & 15) * 4;
            int s   = s0 + row;
            float zi = zinv[bh * T_ + s];
            float4 v4 = *reinterpret_cast<const float4*>(
                V + ((size_t)bh * T_ + s) * D_ + c4);
            Vs[row][c4 + 0] = v4.x * zi;
            Vs[row][c4 + 1] = v4.y * zi;
            Vs[row][c4 + 2] = v4.z * zi;
            Vs[row][c4 + 3] = v4.w * zi;
        }
        __syncthreads();

        #pragma unroll 8
        for (int kk = 0; kk < 32; kk++) {
            float a[4], b[4];
            #pragma unroll
            for (int i = 0; i < 4; i++) a[i] = Ps[kk][ty * 4 + i];
            #pragma unroll
            for (int j = 0; j < 4; j++) b[j] = Vs[kk][tx * 4 + j];
            #pragma unroll
            for (int i = 0; i < 4; i++)
                #pragma unroll
                for (int j = 0; j < 4; j++)
                    acc[i][j] = fmaf(a[i], b[j], acc[i][j]);
        }
        __syncthreads();
    }

    // write (B,T,H,D) head-major concat
    #pragma unroll
    for (int i = 0; i < 4; i++) {
        int t = t0 + ty * 4 + i;
        float* op = out + (((size_t)bb * T_ + t) * H_ + h) * D_ + tx * 4;
        #pragma unroll
        for (int j = 0; j < 4; j++)
            op[j] = acc[i][j];
    }
}

// ---------------------------------------------------------------------------
// Launch
// ---------------------------------------------------------------------------
extern "C" void kernel_launch(void* const* d_in, const int* in_sizes, int n_in,
                              void* d_out, int out_size)
{
    const float* X   = (const float*)d_in[0];
    const float* k_w = (const float*)d_in[1];
    const float* k_b = (const float*)d_in[2];
    const float* q_w = (const float*)d_in[3];
    const float* q_b = (const float*)d_in[4];
    const float* v_w = (const float*)d_in[5];
    const float* v_b = (const float*)d_in[6];
    float* out = (float*)d_out;

    float *pq, *pk, *pv, *ps, *pz;
    cudaGetSymbolAddress((void**)&pq, g_q);
    cudaGetSymbolAddress((void**)&pk, g_k);
    cudaGetSymbolAddress((void**)&pv, g_v);
    cudaGetSymbolAddress((void**)&ps, g_s);
    cudaGetSymbolAddress((void**)&pz, g_zinv);

    dim3 projGrid(B_ * T_ / 64, H_);          // (64, 16)
    proj_kernel<<<projGrid, 256>>>(X, q_w, q_b, pq);
    proj_kernel<<<projGrid, 256>>>(X, k_w, k_b, pk);
    proj_kernel<<<projGrid, 256>>>(X, v_w, v_b, pv);

    dim3 scGrid(T_ / 64, T_ / 64, BH_);       // (32, 32, 32)
    scores_kernel<<<scGrid, 256>>>(pq, pk, ps);

    colstats_kernel<<<BH_ * T_ / 256, 256>>>(ps, pz);

    dim3 pvGrid(T_ / 64, BH_);                // (32, 32)
    pv_kernel<<<pvGrid, 256>>>(ps, pv, pz, out);
}

// round 2
// speedup vs baseline: 1.5650x; 1.5650x over previous
#include <cuda_runtime.h>
#include <cstdint>
#include <math.h>

#define B_  2
#define T_  2048
#define E_  1024
#define H_  16
#define D_  64
#define BH_ (B_*H_)       // 32

// ---------------------------------------------------------------------------
// Device scratch
// ---------------------------------------------------------------------------
__device__ float g_q[(size_t)BH_ * T_ * D_];
__device__ float g_k[(size_t)BH_ * T_ * D_];
__device__ float g_v[(size_t)BH_ * T_ * D_];
__device__ float g_s[(size_t)BH_ * T_ * T_];     // scores -> exp(scores - colmax)
__device__ float g_zinv[(size_t)BH_ * T_];

// ---------------------------------------------------------------------------
// tf32 helpers
// ---------------------------------------------------------------------------
__device__ __forceinline__ uint32_t f2tf(float f) {
    uint32_t u;
    asm("cvt.rna.tf32.f32 %0, %1;" : "=r"(u) : "f"(f));
    return u;
}

__device__ __forceinline__ void mma8(float* c, const uint32_t* a, const uint32_t* b) {
    asm volatile(
        "mma.sync.aligned.m16n8k8.row.col.f32.tf32.tf32.f32 "
        "{%0,%1,%2,%3},{%4,%5,%6,%7},{%8,%9},{%0,%1,%2,%3};"
        : "+f"(c[0]), "+f"(c[1]), "+f"(c[2]), "+f"(c[3])
        : "r"(a[0]), "r"(a[1]), "r"(a[2]), "r"(a[3]), "r"(b[0]), "r"(b[1]));
}

// ---------------------------------------------------------------------------
// Kernel 1: projection out[b,h,t,d] = X[b,t,:] @ W[h,:,d] + bias[h,d]
// Block 128(M) x 64(N=D), 4 warps (64x32 warp tiles), K-tile 32, tf32 MMA.
// ---------------------------------------------------------------------------
__global__ __launch_bounds__(128) void proj_kernel(const float* __restrict__ X,
                                                   const float* __restrict__ W,
                                                   const float* __restrict__ bias,
                                                   float* __restrict__ out)
{
    __shared__ uint32_t As[128][36];   // [m][k], stride 36 == 4 (mod 32): frag-load conflict-free
    __shared__ uint32_t Bs[64][36];    // [n=d][k=e]

    const int m0   = blockIdx.x * 128;
    const int h    = blockIdx.y;
    const int tid  = threadIdx.x;
    const int lane = tid & 31;
    const int warp = tid >> 5;
    const int wm   = warp >> 1;        // 0..1
    const int wn   = warp & 1;         // 0..1
    const int g    = lane >> 2;
    const int tg   = lane & 3;

    float acc[4][4][4] = {};

    for (int k0 = 0; k0 < E_; k0 += 32) {
        // A fill: 128x32 floats = 1024 float4, 8 per thread (coalesced)
        #pragma unroll
        for (int j = 0; j < 8; j++) {
            int q = tid + j * 128;
            int row = q >> 3, c = (q & 7) * 4;
            float4 v = *reinterpret_cast<const float4*>(
                X + (size_t)(m0 + row) * E_ + k0 + c);
            As[row][c + 0] = f2tf(v.x);
            As[row][c + 1] = f2tf(v.y);
            As[row][c + 2] = f2tf(v.z);
            As[row][c + 3] = f2tf(v.w);
        }
        // B fill: W[h][k0+e][d] transposed into Bs[d][e]
        {
            int e = tid & 31, dseg = tid >> 5;
            const float* wp = W + ((size_t)h * E_ + k0 + e) * D_ + dseg * 16;
            #pragma unroll
            for (int i = 0; i < 4; i++) {
                float4 v = *reinterpret_cast<const float4*>(wp + 4 * i);
                int d = dseg * 16 + 4 * i;
                Bs[d + 0][e] = f2tf(v.x);
                Bs[d + 1][e] = f2tf(v.y);
                Bs[d + 2][e] = f2tf(v.z);
                Bs[d + 3][e] = f2tf(v.w);
            }
        }
        __syncthreads();

        #pragma unroll
        for (int ks = 0; ks < 4; ks++) {
            uint32_t a[4][4], b[4][2];
            #pragma unroll
            for (int mf = 0; mf < 4; mf++) {
                int r = wm * 64 + mf * 16 + g;
                a[mf][0] = As[r][ks * 8 + tg];
                a[mf][1] = As[r + 8][ks * 8 + tg];
                a[mf][2] = As[r][ks * 8 + tg + 4];
                a[mf][3] = As[r + 8][ks * 8 + tg + 4];
            }
            #pragma unroll
            for (int nf = 0; nf < 4; nf++) {
                int cn = wn * 32 + nf * 8 + g;
                b[nf][0] = Bs[cn][ks * 8 + tg];
                b[nf][1] = Bs[cn][ks * 8 + tg + 4];
            }
            #pragma unroll
            for (int mf = 0; mf < 4; mf++)
                #pragma unroll
                for (int nf = 0; nf < 4; nf++)
                    mma8(acc[mf][nf], a[mf], b[nf]);
        }
        __syncthreads();
    }

    // epilogue: out (B,H,T,D) + bias
    #pragma unroll
    for (int mf = 0; mf < 4; mf++) {
        #pragma unroll
        for (int half = 0; half < 2; half++) {
            int m  = m0 + wm * 64 + mf * 16 + g + half * 8;
            int bb = m >> 11;
            int t  = m & (T_ - 1);
            #pragma unroll
            for (int nf = 0; nf < 4; nf++) {
                int d = wn * 32 + nf * 8 + 2 * tg;
                float2 val;
                val.x = acc[mf][nf][half * 2 + 0] + bias[h * D_ + d];
                val.y = acc[mf][nf][half * 2 + 1] + bias[h * D_ + d + 1];
                *reinterpret_cast<float2*>(
                    out + (((size_t)bb * H_ + h) * T_ + t) * D_ + d) = val;
            }
        }
    }
}

// ---------------------------------------------------------------------------
// Kernel 2: scores S[bh,t,s] = scale * Q[bh,t,:] . K[bh,s,:]
// Block 128(t) x 128(s), 8 warps (64x32 warp tiles), K=D=64 in 2 tiles of 32.
// ---------------------------------------------------------------------------
__global__ __launch_bounds__(256) void scores_kernel(const float* __restrict__ Q,
                                                     const float* __restrict__ K,
                                                     float* __restrict__ S)
{
    const int st = blockIdx.x;
    const int tt = blockIdx.y;
    const int bh = blockIdx.z;
    if (st > tt) return;

    __shared__ uint32_t Qs[128][36];   // [t][d]
    __shared__ uint32_t Ks[128][36];   // [s][d]  (B operand [n][k])

    const int tid  = threadIdx.x;
    const int lane = tid & 31;
    const int warp = tid >> 5;
    const int wm   = warp >> 2;        // 0..1
    const int wn   = warp & 3;         // 0..3
    const int g    = lane >> 2;
    const int tg   = lane & 3;

    const float* Qp = Q + ((size_t)bh * T_ + tt * 128) * D_;
    const float* Kp = K + ((size_t)bh * T_ + st * 128) * D_;

    float acc[4][4][4] = {};

    for (int k0 = 0; k0 < D_; k0 += 32) {
        #pragma unroll
        for (int j = 0; j < 4; j++) {   // 1024 float4 / 256 threads
            int q = tid + j * 256;
            int row = q >> 3, c = (q & 7) * 4;
            float4 v = *reinterpret_cast<const float4*>(Qp + (size_t)row * D_ + k0 + c);
            Qs[row][c + 0] = f2tf(v.x);
            Qs[row][c + 1] = f2tf(v.y);
            Qs[row][c + 2] = f2tf(v.z);
            Qs[row][c + 3] = f2tf(v.w);
            float4 u = *reinterpret_cast<const float4*>(Kp + (size_t)row * D_ + k0 + c);
            Ks[row][c + 0] = f2tf(u.x);
            Ks[row][c + 1] = f2tf(u.y);
            Ks[row][c + 2] = f2tf(u.z);
            Ks[row][c + 3] = f2tf(u.w);
        }
        __syncthreads();

        #pragma unroll
        for (int ks = 0; ks < 4; ks++) {
            uint32_t a[4][4], b[4][2];
            #pragma unroll
            for (int mf = 0; mf < 4; mf++) {
                int r = wm * 64 + mf * 16 + g;
                a[mf][0] = Qs[r][ks * 8 + tg];
                a[mf][1] = Qs[r + 8][ks * 8 + tg];
                a[mf][2] = Qs[r][ks * 8 + tg + 4];
                a[mf][3] = Qs[r + 8][ks * 8 + tg + 4];
            }
            #pragma unroll
            for (int nf = 0; nf < 4; nf++) {
                int cn = wn * 32 + nf * 8 + g;
                b[nf][0] = Ks[cn][ks * 8 + tg];
                b[nf][1] = Ks[cn][ks * 8 + tg + 4];
            }
            #pragma unroll
            for (int mf = 0; mf < 4; mf++)
                #pragma unroll
                for (int nf = 0; nf < 4; nf++)
                    mma8(acc[mf][nf], a[mf], b[nf]);
        }
        __syncthreads();
    }

    const float scale = 0.125f;
    #pragma unroll
    for (int mf = 0; mf < 4; mf++) {
        #pragma unroll
        for (int half = 0; half < 2; half++) {
            int t = tt * 128 + wm * 64 + mf * 16 + g + half * 8;
            #pragma unroll
            for (int nf = 0; nf < 4; nf++) {
                int s = st * 128 + wn * 32 + nf * 8 + 2 * tg;
                float2 val;
                val.x = acc[mf][nf][half * 2 + 0] * scale;
                val.y = acc[mf][nf][half * 2 + 1] * scale;
                *reinterpret_cast<float2*>(
                    S + ((size_t)bh * T_ + t) * T_ + s) = val;
            }
        }
    }
}

// ---------------------------------------------------------------------------
// Kernel 3: column softmax stats (softmax over QUERY axis t, valid t >= s).
// ---------------------------------------------------------------------------
__global__ void colstats_kernel(float* __restrict__ S,
                                float* __restrict__ zinv)
{
    const int idx = blockIdx.x * blockDim.x + threadIdx.x;
    const int bh  = idx >> 11;
    const int s   = idx & (T_ - 1);
    float* Sp = S + (size_t)bh * T_ * T_ + s;

    const int t0 = s & ~31;

    float m = -3.0e38f;
    for (int t = t0; t < T_; t++) {
        if (t >= s) m = fmaxf(m, Sp[(size_t)t * T_]);
    }
    float z = 0.f;
    for (int t = t0; t < T_; t++) {
        if (t >= s) {
            float e = __expf(Sp[(size_t)t * T_] - m);
            z += e;
            Sp[(size_t)t * T_] = e;
        }
    }
    zinv[idx] = 1.0f / z;
}

// ---------------------------------------------------------------------------
// Kernel 4: out = P @ (V * zinv), causal. Block 128(t) x 64(d), 4 warps.
// ---------------------------------------------------------------------------
__global__ __launch_bounds__(128) void pv_kernel(const float* __restrict__ S,
                                                 const float* __restrict__ V,
                                                 const float* __restrict__ zinv,
                                                 float* __restrict__ out)
{
    const int tt = blockIdx.x;
    const int bh = blockIdx.y;
    const int bb = bh >> 4;
    const int h  = bh & 15;

    __shared__ uint32_t Ps[128][36];   // [t][s]  (A operand [m][k])
    __shared__ uint32_t Vs[32][72];    // [s][d]  (B operand [k][n], stride 72 == 8 mod 32)

    const int tid  = threadIdx.x;
    const int lane = tid & 31;
    const int warp = tid >> 5;
    const int wm   = warp >> 1;
    const int wn   = warp & 1;
    const int g    = lane >> 2;
    const int tg   = lane & 3;
    const int t0   = tt * 128;

    const float* Sb = S + (size_t)bh * T_ * T_;

    float acc[4][4][4] = {};

    for (int s0 = 0; s0 < t0 + 128; s0 += 32) {
        // P tile fill with causal mask (s <= t)
        #pragma unroll
        for (int j = 0; j < 8; j++) {
            int q = tid + j * 128;
            int row = q >> 3, c = (q & 7) * 4;
            int t = t0 + row;
            float4 v = *reinterpret_cast<const float4*>(Sb + (size_t)t * T_ + s0 + c);
            int sb = s0 + c;
            Ps[row][c + 0] = f2tf((sb + 0 <= t) ? v.x : 0.f);
            Ps[row][c + 1] = f2tf((sb + 1 <= t) ? v.y : 0.f);
            Ps[row][c + 2] = f2tf((sb + 2 <= t) ? v.z : 0.f);
            Ps[row][c + 3] = f2tf((sb + 3 <= t) ? v.w : 0.f);
        }
        // V tile fill scaled by zinv
        #pragma unroll
        for (int j = 0; j < 4; j++) {
            int q = tid + j * 128;
            int s = q >> 4, dq = (q & 15) * 4;
            float zi = zinv[bh * T_ + s0 + s];
            float4 v = *reinterpret_cast<const float4*>(
                V + ((size_t)bh * T_ + s0 + s) * D_ + dq);
            Vs[s][dq + 0] = f2tf(v.x * zi);
            Vs[s][dq + 1] = f2tf(v.y * zi);
            Vs[s][dq + 2] = f2tf(v.z * zi);
            Vs[s][dq + 3] = f2tf(v.w * zi);
        }
        __syncthreads();

        #pragma unroll
        for (int ks = 0; ks < 4; ks++) {
            uint32_t a[4][4], b[4][2];
            #pragma unroll
            for (int mf = 0; mf < 4; mf++) {
                int r = wm * 64 + mf * 16 + g;
                a[mf][0] = Ps[r][ks * 8 + tg];
                a[mf][1] = Ps[r + 8][ks * 8 + tg];
                a[mf][2] = Ps[r][ks * 8 + tg + 4];
                a[mf][3] = Ps[r + 8][ks * 8 + tg + 4];
            }
            #pragma unroll
            for (int nf = 0; nf < 4; nf++) {
                int cn = wn * 32 + nf * 8 + g;
                b[nf][0] = Vs[ks * 8 + tg][cn];
                b[nf][1] = Vs[ks * 8 + tg + 4][cn];
            }
            #pragma unroll
            for (int mf = 0; mf < 4; mf++)
                #pragma unroll
                for (int nf = 0; nf < 4; nf++)
                    mma8(acc[mf][nf], a[mf], b[nf]);
        }
        __syncthreads();
    }

    // epilogue: (B,T,H,D) head-major concat
    #pragma unroll
    for (int mf = 0; mf < 4; mf++) {
        #pragma unroll
        for (int half = 0; half < 2; half++) {
            int t = t0 + wm * 64 + mf * 16 + g + half * 8;
            #pragma unroll
            for (int nf = 0; nf < 4; nf++) {
                int d = wn * 32 + nf * 8 + 2 * tg;
                float2 val;
                val.x = acc[mf][nf][half * 2 + 0];
                val.y = acc[mf][nf][half * 2 + 1];
                *reinterpret_cast<float2*>(
                    out + (((size_t)bb * T_ + t) * H_ + h) * D_ + d) = val;
            }
        }
    }
}

// ---------------------------------------------------------------------------
// Launch
// ---------------------------------------------------------------------------
extern "C" void kernel_launch(void* const* d_in, const int* in_sizes, int n_in,
                              void* d_out, int out_size)
{
    const float* X   = (const float*)d_in[0];
    const float* k_w = (const float*)d_in[1];
    const float* k_b = (const float*)d_in[2];
    const float* q_w = (const float*)d_in[3];
    const float* q_b = (const float*)d_in[4];
    const float* v_w = (const float*)d_in[5];
    const float* v_b = (const float*)d_in[6];
    float* out = (float*)d_out;

    float *pq, *pk, *pv, *ps, *pz;
    cudaGetSymbolAddress((void**)&pq, g_q);
    cudaGetSymbolAddress((void**)&pk, g_k);
    cudaGetSymbolAddress((void**)&pv, g_v);
    cudaGetSymbolAddress((void**)&ps, g_s);
    cudaGetSymbolAddress((void**)&pz, g_zinv);

    dim3 projGrid(B_ * T_ / 128, H_);          // (32, 16)
    proj_kernel<<<projGrid, 128>>>(X, q_w, q_b, pq);
    proj_kernel<<<projGrid, 128>>>(X, k_w, k_b, pk);
    proj_kernel<<<projGrid, 128>>>(X, v_w, v_b, pv);

    dim3 scGrid(T_ / 128, T_ / 128, BH_);      // (16, 16, 32)
    scores_kernel<<<scGrid, 256>>>(pq, pk, ps);

    colstats_kernel<<<BH_ * T_ / 256, 256>>>(ps, pz);

    dim3 pvGrid(T_ / 128, BH_);                // (16, 32)
    pv_kernel<<<pvGrid, 128>>>(ps, pv, pz, out);
}

// round 4
// speedup vs baseline: 4.6646x; 2.9806x over previous
#include <cuda_runtime.h>
#include <cstdint>
#include <math.h>

#define B_  2
#define T_  2048
#define E_  1024
#define H_  16
#define D_  64
#define BH_ (B_*H_)       // 32

// ---------------------------------------------------------------------------
// Device scratch
// ---------------------------------------------------------------------------
__device__ float g_q[(size_t)BH_ * T_ * D_];
__device__ float g_k[(size_t)BH_ * T_ * D_];
__device__ float g_v[(size_t)BH_ * T_ * D_];
__device__ float g_m[(size_t)BH_ * T_];       // column max
__device__ float g_zinv[(size_t)BH_ * T_];    // column 1/sum

// ---------------------------------------------------------------------------
// tf32 helpers
// ---------------------------------------------------------------------------
__device__ __forceinline__ uint32_t f2tf(float f) {
    uint32_t u;
    asm("cvt.rna.tf32.f32 %0, %1;" : "=r"(u) : "f"(f));
    return u;
}

__device__ __forceinline__ void mma8(float* c, const uint32_t* a, const uint32_t* b) {
    asm volatile(
        "mma.sync.aligned.m16n8k8.row.col.f32.tf32.tf32.f32 "
        "{%0,%1,%2,%3},{%4,%5,%6,%7},{%8,%9},{%0,%1,%2,%3};"
        : "+f"(c[0]), "+f"(c[1]), "+f"(c[2]), "+f"(c[3])
        : "r"(a[0]), "r"(a[1]), "r"(a[2]), "r"(a[3]), "r"(b[0]), "r"(b[1]));
}

// ---------------------------------------------------------------------------
// Kernel 1: fused QKV projection. blockIdx.z selects Q/K/V.
// Block 128(M) x 64(N=D), 4 warps (64x32 warp tiles), K-tile 32.
// ---------------------------------------------------------------------------
__global__ __launch_bounds__(128) void proj_kernel(const float* __restrict__ X,
                                                   const float* __restrict__ qw,
                                                   const float* __restrict__ kw,
                                                   const float* __restrict__ vw,
                                                   const float* __restrict__ qb,
                                                   const float* __restrict__ kb,
                                                   const float* __restrict__ vb,
                                                   float* __restrict__ oq,
                                                   float* __restrict__ ok,
                                                   float* __restrict__ ov)
{
    const float* W; const float* bias; float* out;
    if (blockIdx.z == 0)      { W = qw; bias = qb; out = oq; }
    else if (blockIdx.z == 1) { W = kw; bias = kb; out = ok; }
    else                      { W = vw; bias = vb; out = ov; }

    __shared__ uint32_t As[128][36];   // [m][k]
    __shared__ uint32_t Bs[64][36];    // [n=d][k=e]

    const int m0   = blockIdx.x * 128;
    const int h    = blockIdx.y;
    const int tid  = threadIdx.x;
    const int lane = tid & 31;
    const int warp = tid >> 5;
    const int wm   = warp >> 1;
    const int wn   = warp & 1;
    const int g    = lane >> 2;
    const int tg   = lane & 3;

    float acc[4][4][4] = {};

    for (int k0 = 0; k0 < E_; k0 += 32) {
        #pragma unroll
        for (int j = 0; j < 8; j++) {
            int q = tid + j * 128;
            int row = q >> 3, c = (q & 7) * 4;
            float4 v = *reinterpret_cast<const float4*>(
                X + (size_t)(m0 + row) * E_ + k0 + c);
            As[row][c + 0] = f2tf(v.x);
            As[row][c + 1] = f2tf(v.y);
            As[row][c + 2] = f2tf(v.z);
            As[row][c + 3] = f2tf(v.w);
        }
        {
            int e = tid & 31, dseg = tid >> 5;
            const float* wp = W + ((size_t)h * E_ + k0 + e) * D_ + dseg * 16;
            #pragma unroll
            for (int i = 0; i < 4; i++) {
                float4 v = *reinterpret_cast<const float4*>(wp + 4 * i);
                int d = dseg * 16 + 4 * i;
                Bs[d + 0][e] = f2tf(v.x);
                Bs[d + 1][e] = f2tf(v.y);
                Bs[d + 2][e] = f2tf(v.z);
                Bs[d + 3][e] = f2tf(v.w);
            }
        }
        __syncthreads();

        #pragma unroll
        for (int ks = 0; ks < 4; ks++) {
            uint32_t a[4][4], b[4][2];
            #pragma unroll
            for (int mf = 0; mf < 4; mf++) {
                int r = wm * 64 + mf * 16 + g;
                a[mf][0] = As[r][ks * 8 + tg];
                a[mf][1] = As[r + 8][ks * 8 + tg];
                a[mf][2] = As[r][ks * 8 + tg + 4];
                a[mf][3] = As[r + 8][ks * 8 + tg + 4];
            }
            #pragma unroll
            for (int nf = 0; nf < 4; nf++) {
                int cn = wn * 32 + nf * 8 + g;
                b[nf][0] = Bs[cn][ks * 8 + tg];
                b[nf][1] = Bs[cn][ks * 8 + tg + 4];
            }
            #pragma unroll
            for (int mf = 0; mf < 4; mf++)
                #pragma unroll
                for (int nf = 0; nf < 4; nf++)
                    mma8(acc[mf][nf], a[mf], b[nf]);
        }
        __syncthreads();
    }

    #pragma unroll
    for (int mf = 0; mf < 4; mf++) {
        #pragma unroll
        for (int half = 0; half < 2; half++) {
            int m  = m0 + wm * 64 + mf * 16 + g + half * 8;
            int bb = m >> 11;
            int t  = m & (T_ - 1);
            #pragma unroll
            for (int nf = 0; nf < 4; nf++) {
                int d = wn * 32 + nf * 8 + 2 * tg;
                float2 val;
                val.x = acc[mf][nf][half * 2 + 0] + bias[h * D_ + d];
                val.y = acc[mf][nf][half * 2 + 1] + bias[h * D_ + d + 1];
                *reinterpret_cast<float2*>(
                    out + (((size_t)bb * H_ + h) * T_ + t) * D_ + d) = val;
            }
        }
    }
}

// ---------------------------------------------------------------------------
// Pass A: column softmax stats without materializing S.
// grid (s_tile=16, bh=32), block 256. K s-tile resident; loop t-tiles,
// recompute QK^T, online column max/sum reduction.
// Warp tiling: 8 warps, warp = 64t x 32s (wm=warp>>2, wn=warp&3).
// ---------------------------------------------------------------------------
__global__ __launch_bounds__(256) void stats_kernel(const float* __restrict__ Q,
                                                    const float* __restrict__ K,
                                                    float* __restrict__ m_out,
                                                    float* __restrict__ z_out)
{
    extern __shared__ char smem_raw[];
    uint32_t* Ks = reinterpret_cast<uint32_t*>(smem_raw);                 // [128][68]
    uint32_t* Qs = Ks + 128 * 68;                                         // [128][68]
    float* redm = reinterpret_cast<float*>(Qs + 128 * 68);                // [2][128]
    float* redz = redm + 256;                                             // [2][128]
    float* mrun = redz + 256;                                             // [128]
    float* zrun = mrun + 128;                                             // [128]

    const int st   = blockIdx.x;
    const int bh   = blockIdx.y;
    const int tid  = threadIdx.x;
    const int lane = tid & 31;
    const int warp = tid >> 5;
    const int wm   = warp >> 2;     // 0..1
    const int wn   = warp & 3;      // 0..3
    const int g    = lane >> 2;
    const int tg   = lane & 3;

    // load K s-tile once
    const float* Kp = K + ((size_t)bh * T_ + st * 128) * D_;
    #pragma unroll
    for (int j = 0; j < 8; j++) {
        int q = tid + j * 256;
        int row = q >> 4, c = (q & 15) * 4;
        float4 v = *reinterpret_cast<const float4*>(Kp + (size_t)row * D_ + c);
        Ks[row * 68 + c + 0] = f2tf(v.x);
        Ks[row * 68 + c + 1] = f2tf(v.y);
        Ks[row * 68 + c + 2] = f2tf(v.z);
        Ks[row * 68 + c + 3] = f2tf(v.w);
    }
    if (tid < 128) { mrun[tid] = -3.0e38f; zrun[tid] = 0.f; }
    __syncthreads();

    const float scale = 0.125f;

    for (int it = st; it < T_ / 128; it++) {
        // load Q t-tile
        const float* Qp = Q + ((size_t)bh * T_ + it * 128) * D_;
        #pragma unroll
        for (int j = 0; j < 8; j++) {
            int q = tid + j * 256;
            int row = q >> 4, c = (q & 15) * 4;
            float4 v = *reinterpret_cast<const float4*>(Qp + (size_t)row * D_ + c);
            Qs[row * 68 + c + 0] = f2tf(v.x);
            Qs[row * 68 + c + 1] = f2tf(v.y);
            Qs[row * 68 + c + 2] = f2tf(v.z);
            Qs[row * 68 + c + 3] = f2tf(v.w);
        }
        __syncthreads();

        float acc[4][4][4] = {};
        #pragma unroll
        for (int ks = 0; ks < 8; ks++) {
            uint32_t a[4][4], b[4][2];
            #pragma unroll
            for (int mf = 0; mf < 4; mf++) {
                int r = wm * 64 + mf * 16 + g;
                a[mf][0] = Qs[r * 68 + ks * 8 + tg];
                a[mf][1] = Qs[(r + 8) * 68 + ks * 8 + tg];
                a[mf][2] = Qs[r * 68 + ks * 8 + tg + 4];
                a[mf][3] = Qs[(r + 8) * 68 + ks * 8 + tg + 4];
            }
            #pragma unroll
            for (int nf = 0; nf < 4; nf++) {
                int cn = wn * 32 + nf * 8 + g;
                b[nf][0] = Ks[cn * 68 + ks * 8 + tg];
                b[nf][1] = Ks[cn * 68 + ks * 8 + tg + 4];
            }
            #pragma unroll
            for (int mf = 0; mf < 4; mf++)
                #pragma unroll
                for (int nf = 0; nf < 4; nf++)
                    mma8(acc[mf][nf], a[mf], b[nf]);
        }

        // scale + causal mask (diag tile only)
        if (it == st) {
            #pragma unroll
            for (int mf = 0; mf < 4; mf++)
                #pragma unroll
                for (int hh = 0; hh < 2; hh++) {
                    int tl = wm * 64 + mf * 16 + g + hh * 8;
                    #pragma unroll
                    for (int nf = 0; nf < 4; nf++)
                        #pragma unroll
                        for (int ci = 0; ci < 2; ci++) {
                            int sl = wn * 32 + nf * 8 + 2 * tg + ci;
                            float x = acc[mf][nf][hh * 2 + ci] * scale;
                            acc[mf][nf][hh * 2 + ci] = (tl >= sl) ? x : -3.0e38f;
                        }
                }
        } else {
            #pragma unroll
            for (int mf = 0; mf < 4; mf++)
                #pragma unroll
                for (int nf = 0; nf < 4; nf++)
                    #pragma unroll
                    for (int c = 0; c < 4; c++)
                        acc[mf][nf][c] *= scale;
        }

        // per-warp column max -> redm
        #pragma unroll
        for (int nf = 0; nf < 4; nf++)
            #pragma unroll
            for (int ci = 0; ci < 2; ci++) {
                float v = -3.0e38f;
                #pragma unroll
                for (int mf = 0; mf < 4; mf++) {
                    v = fmaxf(v, acc[mf][nf][ci]);
                    v = fmaxf(v, acc[mf][nf][2 + ci]);
                }
                v = fmaxf(v, __shfl_xor_sync(0xffffffffu, v, 4));
                v = fmaxf(v, __shfl_xor_sync(0xffffffffu, v, 8));
                v = fmaxf(v, __shfl_xor_sync(0xffffffffu, v, 16));
                if (lane < 4) redm[wm * 128 + wn * 32 + nf * 8 + 2 * tg + ci] = v;
            }
        __syncthreads();

        // exp-sum with combined tile max
        #pragma unroll
        for (int nf = 0; nf < 4; nf++)
            #pragma unroll
            for (int ci = 0; ci < 2; ci++) {
                int col = wn * 32 + nf * 8 + 2 * tg + ci;
                float mt = fmaxf(redm[col], redm[128 + col]);
                float zs = 0.f;
                #pragma unroll
                for (int mf = 0; mf < 4; mf++) {
                    zs += __expf(acc[mf][nf][ci] - mt);
                    zs += __expf(acc[mf][nf][2 + ci] - mt);
                }
                zs += __shfl_xor_sync(0xffffffffu, zs, 4);
                zs += __shfl_xor_sync(0xffffffffu, zs, 8);
                zs += __shfl_xor_sync(0xffffffffu, zs, 16);
                if (lane < 4) redz[wm * 128 + col] = zs;
            }
        __syncthreads();

        // online combine into running stats
        if (tid < 128) {
            float mt = fmaxf(redm[tid], redm[128 + tid]);
            float zt = redz[tid] + redz[128 + tid];
            float mo = mrun[tid];
            float mn = fmaxf(mo, mt);
            zrun[tid] = zrun[tid] * __expf(mo - mn) + zt * __expf(mt - mn);
            mrun[tid] = mn;
        }
        __syncthreads();
    }

    if (tid < 128) {
        int s = st * 128 + tid;
        m_out[bh * T_ + s] = mrun[tid];
        z_out[bh * T_ + s] = 1.0f / zrun[tid];
    }
}

// ---------------------------------------------------------------------------
// Pass B: out[t,d] = sum_{s<=t} exp(S[t,s]-m[s])*zinv[s]*V[s,d], S recomputed.
// grid (t_tile=16 [reversed for load balance], bh=32), block 256.
// QK warp tiling: 8 warps, 64t x 16s. PV warp tiling: 8 warps, 32t x 32d.
// ---------------------------------------------------------------------------
__global__ __launch_bounds__(256) void out_kernel(const float* __restrict__ Q,
                                                  const float* __restrict__ K,
                                                  const float* __restrict__ V,
                                                  const float* __restrict__ mcol_g,
                                                  const float* __restrict__ zcol_g,
                                                  float* __restrict__ out)
{
    extern __shared__ char smem_raw[];
    uint32_t* Qs = reinterpret_cast<uint32_t*>(smem_raw);  // [128][68]
    uint32_t* Ps = Qs + 128 * 68;                          // [128][68]
    uint32_t* Ks = Ps + 128 * 68;                          // [64][68]
    uint32_t* Vs = Ks + 64 * 68;                           // [64][72]  (64 d-cols + pad 8)
    float* mcol  = reinterpret_cast<float*>(Vs + 64 * 72); // [64]
    float* zcol  = mcol + 64;                              // [64]

    const int tt   = (T_ / 128 - 1) - blockIdx.x;   // heavy blocks first
    const int bh   = blockIdx.y;
    const int bb   = bh >> 4;
    const int h    = bh & 15;
    const int tid  = threadIdx.x;
    const int lane = tid & 31;
    const int warp = tid >> 5;
    const int g    = lane >> 2;
    const int tg   = lane & 3;

    const int wq_m = warp >> 2, wq_n = warp & 3;
    const int wp_m = warp & 3,  wp_n = warp >> 2;

    const int t0 = tt * 128;

    // load Q tile once
    const float* Qp = Q + ((size_t)bh * T_ + t0) * D_;
    #pragma unroll
    for (int j = 0; j < 8; j++) {
        int q = tid + j * 256;
        int row = q >> 4, c = (q & 15) * 4;
        float4 v = *reinterpret_cast<const float4*>(Qp + (size_t)row * D_ + c);
        Qs[row * 68 + c + 0] = f2tf(v.x);
        Qs[row * 68 + c + 1] = f2tf(v.y);
        Qs[row * 68 + c + 2] = f2tf(v.z);
        Qs[row * 68 + c + 3] = f2tf(v.w);
    }

    float oacc[2][4][4] = {};
    const float scale = 0.125f;

    for (int s0 = 0; s0 <= t0 + 64; s0 += 64) {
        __syncthreads();   // prev PV done; Q load done on first iter

        // load K,V chunk (64 rows) + column stats
        const float* Kp = K + ((size_t)bh * T_ + s0) * D_;
        const float* Vp = V + ((size_t)bh * T_ + s0) * D_;
        #pragma unroll
        for (int j = 0; j < 4; j++) {
            int q = tid + j * 256;
            int row = q >> 4, c = (q & 15) * 4;
            float4 kv = *reinterpret_cast<const float4*>(Kp + (size_t)row * D_ + c);
            Ks[row * 68 + c + 0] = f2tf(kv.x);
            Ks[row * 68 + c + 1] = f2tf(kv.y);
            Ks[row * 68 + c + 2] = f2tf(kv.z);
            Ks[row * 68 + c + 3] = f2tf(kv.w);
            float4 vv = *reinterpret_cast<const float4*>(Vp + (size_t)row * D_ + c);
            Vs[row * 72 + c + 0] = f2tf(vv.x);
            Vs[row * 72 + c + 1] = f2tf(vv.y);
            Vs[row * 72 + c + 2] = f2tf(vv.z);
            Vs[row * 72 + c + 3] = f2tf(vv.w);
        }
        if (tid < 64) {
            mcol[tid] = mcol_g[bh * T_ + s0 + tid];
            zcol[tid] = zcol_g[bh * T_ + s0 + tid];
        }
        __syncthreads();

        // QK chunk: 128t x 64s
        float sacc[4][2][4] = {};
        #pragma unroll
        for (int ks = 0; ks < 8; ks++) {
            uint32_t a[4][4], b[2][2];
            #pragma unroll
            for (int mf = 0; mf < 4; mf++) {
                int r = wq_m * 64 + mf * 16 + g;
                a[mf][0] = Qs[r * 68 + ks * 8 + tg];
                a[mf][1] = Qs[(r + 8) * 68 + ks * 8 + tg];
                a[mf][2] = Qs[r * 68 + ks * 8 + tg + 4];
                a[mf][3] = Qs[(r + 8) * 68 + ks * 8 + tg + 4];
            }
            #pragma unroll
            for (int nf = 0; nf < 2; nf++) {
                int cn = wq_n * 16 + nf * 8 + g;
                b[nf][0] = Ks[cn * 68 + ks * 8 + tg];
                b[nf][1] = Ks[cn * 68 + ks * 8 + tg + 4];
            }
            #pragma unroll
            for (int mf = 0; mf < 4; mf++)
                #pragma unroll
                for (int nf = 0; nf < 2; nf++)
                    mma8(sacc[mf][nf], a[mf], b[nf]);
        }

        // exp + normalize + stage P (tf32) in smem
        const bool needmask = (s0 + 63 > t0);
        #pragma unroll
        for (int mf = 0; mf < 4; mf++)
            #pragma unroll
            for (int hh = 0; hh < 2; hh++) {
                int tl = wq_m * 64 + mf * 16 + g + hh * 8;
                #pragma unroll
                for (int nf = 0; nf < 2; nf++)
                    #pragma unroll
                    for (int ci = 0; ci < 2; ci++) {
                        int sl = wq_n * 16 + nf * 8 + 2 * tg + ci;
                        float x = sacc[mf][nf][hh * 2 + ci] * scale;
                        float p = __expf(x - mcol[sl]) * zcol[sl];
                        if (needmask && (s0 + sl > t0 + tl)) p = 0.f;
                        Ps[tl * 68 + sl] = f2tf(p);
                    }
            }
        __syncthreads();

        // PV: accumulate 128t x 64d over k=64
        #pragma unroll
        for (int ks = 0; ks < 8; ks++) {
            uint32_t a[2][4], b[4][2];
            #pragma unroll
            for (int mf = 0; mf < 2; mf++) {
                int r = wp_m * 32 + mf * 16 + g;
                a[mf][0] = Ps[r * 68 + ks * 8 + tg];
                a[mf][1] = Ps[(r + 8) * 68 + ks * 8 + tg];
                a[mf][2] = Ps[r * 68 + ks * 8 + tg + 4];
                a[mf][3] = Ps[(r + 8) * 68 + ks * 8 + tg + 4];
            }
            #pragma unroll
            for (int nf = 0; nf < 4; nf++) {
                int cn = wp_n * 32 + nf * 8 + g;
                b[nf][0] = Vs[(ks * 8 + tg) * 72 + cn];
                b[nf][1] = Vs[(ks * 8 + tg + 4) * 72 + cn];
            }
            #pragma unroll
            for (int mf = 0; mf < 2; mf++)
                #pragma unroll
                for (int nf = 0; nf < 4; nf++)
                    mma8(oacc[mf][nf], a[mf], b[nf]);
        }
    }

    // epilogue: (B,T,H,D) head-major concat
    #pragma unroll
    for (int mf = 0; mf < 2; mf++)
        #pragma unroll
        for (int hh = 0; hh < 2; hh++) {
            int t = t0 + wp_m * 32 + mf * 16 + g + hh * 8;
            #pragma unroll
            for (int nf = 0; nf < 4; nf++) {
                int d = wp_n * 32 + nf * 8 + 2 * tg;
                float2 val;
                val.x = oacc[mf][nf][hh * 2 + 0];
                val.y = oacc[mf][nf][hh * 2 + 1];
                *reinterpret_cast<float2*>(
                    out + (((size_t)bb * T_ + t) * H_ + h) * D_ + d) = val;
            }
        }
}

// ---------------------------------------------------------------------------
// Launch
// ---------------------------------------------------------------------------
extern "C" void kernel_launch(void* const* d_in, const int* in_sizes, int n_in,
                              void* d_out, int out_size)
{
    const float* X   = (const float*)d_in[0];
    const float* k_w = (const float*)d_in[1];
    const float* k_b = (const float*)d_in[2];
    const float* q_w = (const float*)d_in[3];
    const float* q_b = (const float*)d_in[4];
    const float* v_w = (const float*)d_in[5];
    const float* v_b = (const float*)d_in[6];
    float* out = (float*)d_out;

    float *pq, *pk, *pv, *pm, *pz;
    cudaGetSymbolAddress((void**)&pq, g_q);
    cudaGetSymbolAddress((void**)&pk, g_k);
    cudaGetSymbolAddress((void**)&pv, g_v);
    cudaGetSymbolAddress((void**)&pm, g_m);
    cudaGetSymbolAddress((void**)&pz, g_zinv);

    const int SA = (2 * 128 * 68) * 4 + (256 + 256 + 128 + 128) * 4;            // 72704
    const int SB = (128 * 68 + 128 * 68 + 64 * 68 + 64 * 72) * 4 + 128 * 4;     // 105984

    cudaFuncSetAttribute(stats_kernel, cudaFuncAttributeMaxDynamicSharedMemorySize, SA);
    cudaFuncSetAttribute(out_kernel,   cudaFuncAttributeMaxDynamicSharedMemorySize, SB);

    dim3 projGrid(B_ * T_ / 128, H_, 3);
    proj_kernel<<<projGrid, 128>>>(X, q_w, k_w, v_w, q_b, k_b, v_b, pq, pk, pv);

    dim3 stGrid(T_ / 128, BH_);
    stats_kernel<<<stGrid, 256, SA>>>(pq, pk, pm, pz);

    dim3 outGrid(T_ / 128, BH_);
    out_kernel<<<outGrid, 256, SB>>>(pq, pk, pv, pm, pz, out);
}